// round 4
// baseline (speedup 1.0000x reference)
#include <cuda_runtime.h>
#include <cuda_bf16.h>

// Problem-fixed capacities (N=100000, E=1600000 per setup_inputs)
#define NMAX   100000
#define EMAX   1600000
#define ETOTMX (NMAX + EMAX)
#define EPS    1e-16f

// ---------------- scratch (static device globals; no allocation) -------------
__device__ __align__(16) float g_as1 [NMAX * 4];
__device__ __align__(16) float g_ad1 [NMAX * 4];
__device__ __align__(16) float g_s1  [NMAX * 4];    // L1 softmax denominators
__device__ __align__(16) float g_t1  [NMAX * 4];    // sum p * x[src] per head (rank-1 trick)
__device__ __align__(16) float g_h2  [NMAX * 64];
__device__ __align__(16) float g_as2 [NMAX * 8];
__device__ __align__(16) float g_ad2 [NMAX * 8];
__device__ __align__(16) float g_s2  [NMAX * 8];
__device__ __align__(16) float g_acc2[NMAX * 64];   // unnormalized sum p * h2[src]

// vector global reduction (sm_90+): 4 floats in one L2 transaction
__device__ __forceinline__ void red_add_v4(float* addr, float4 v) {
    asm volatile("red.global.add.v4.f32 [%0], {%1, %2, %3, %4};"
                 :: "l"(addr), "f"(v.x), "f"(v.y), "f"(v.z), "f"(v.w)
                 : "memory");
}

__device__ __forceinline__ float lrelu(float t) { return t > 0.f ? t : 0.2f * t; }
__device__ __forceinline__ float elu(float t)   { return t > 0.f ? t : expm1f(t); }

// ---------------- layer 1 node-side coeffs + zero s1/t1 ----------------------
// h1[i] = x[i] * W1 (rank-1), so a_s[i][hd] = x[i] * (W1[hd]·att_src[hd])
__global__ void k_l1_node(const float* __restrict__ x, const float* __restrict__ W1,
                          const float* __restrict__ atts, const float* __restrict__ attd,
                          int N) {
    int i = blockIdx.x * blockDim.x + threadIdx.x;
    if (i >= N) return;
    float xv = x[i];
    float4 vs, vd;
    float* ps = &vs.x;
    float* pd = &vd.x;
#pragma unroll
    for (int hd = 0; hd < 4; hd++) {
        float cs = 0.f, cd = 0.f;
#pragma unroll
        for (int c = 0; c < 8; c++) {
            float w = __ldg(&W1[hd * 8 + c]);
            cs += w * __ldg(&atts[hd * 8 + c]);
            cd += w * __ldg(&attd[hd * 8 + c]);
        }
        ps[hd] = xv * cs;
        pd[hd] = xv * cd;
    }
    *(float4*)&g_as1[i * 4] = vs;
    *(float4*)&g_ad1[i * 4] = vd;
    float4 z = make_float4(0.f, 0.f, 0.f, 0.f);
    *(float4*)&g_s1[i * 4] = z;
    *(float4*)&g_t1[i * 4] = z;
}

// ---------------- layer 1: single fused edge pass -----------------------------
__global__ void k_l1_edge(const float* __restrict__ x,
                          const int* __restrict__ src, const int* __restrict__ dst,
                          int E, int Etot) {
    int e = blockIdx.x * blockDim.x + threadIdx.x;
    if (e >= Etot) return;
    int s, d;
    if (e < E) { s = src[e]; d = dst[e]; } else { s = d = e - E; }
    float4 as = *(const float4*)&g_as1[s * 4];
    float4 ad = *(const float4*)&g_ad1[d * 4];
    float xs = x[s];
    float4 p;
    p.x = __expf(lrelu(as.x + ad.x));
    p.y = __expf(lrelu(as.y + ad.y));
    p.z = __expf(lrelu(as.z + ad.z));
    p.w = __expf(lrelu(as.w + ad.w));
    red_add_v4(&g_s1[d * 4], p);
    float4 t = make_float4(p.x * xs, p.y * xs, p.z * xs, p.w * xs);
    red_add_v4(&g_t1[d * 4], t);
}

// ---------------- fused mid phase: one thread per node ------------------------
// act1 = elu(t1/(s1+eps) * W1 + b1)  (in registers, never stored)
// h2 = act1 @ W2; as2/ad2 = head-dots; zero s2/acc2.
__global__ __launch_bounds__(128) void k_mid(const float* __restrict__ W1,
                                             const float* __restrict__ b1,
                                             const float* __restrict__ W2,
                                             const float* __restrict__ atts,
                                             const float* __restrict__ attd,
                                             int N) {
    __shared__ float sW1[32], sB1[32], sAs[64], sAd[64];
    __shared__ __align__(16) float sW2[32 * 64];
    for (int j = threadIdx.x; j < 32; j += blockDim.x) { sW1[j] = W1[j]; sB1[j] = b1[j]; }
    for (int j = threadIdx.x; j < 64; j += blockDim.x) { sAs[j] = atts[j]; sAd[j] = attd[j]; }
    for (int j = threadIdx.x; j < 32 * 64 / 4; j += blockDim.x)
        ((float4*)sW2)[j] = ((const float4*)W2)[j];
    __syncthreads();

    int i = blockIdx.x * blockDim.x + threadIdx.x;
    if (i >= N) return;

    float4 s4 = *(const float4*)&g_s1[i * 4];
    float4 t4 = *(const float4*)&g_t1[i * 4];
    const float* sp = &s4.x;
    const float* tp = &t4.x;
    float act[32];
#pragma unroll
    for (int hd = 0; hd < 4; hd++) {
        float base = tp[hd] / (sp[hd] + EPS);
#pragma unroll
        for (int c = 0; c < 8; c++)
            act[hd * 8 + c] = elu(base * sW1[hd * 8 + c] + sB1[hd * 8 + c]);
    }

    float4 as2v[2], ad2v[2];
#pragma unroll
    for (int half = 0; half < 2; half++) {
        float4 acc[8];
#pragma unroll
        for (int j = 0; j < 8; j++) acc[j] = make_float4(0.f, 0.f, 0.f, 0.f);
#pragma unroll
        for (int k = 0; k < 32; k++) {
            float a = act[k];
            const float4* wrow = (const float4*)&sW2[k * 64 + half * 32];
#pragma unroll
            for (int j = 0; j < 8; j++) {
                float4 w = wrow[j];
                acc[j].x += a * w.x; acc[j].y += a * w.y;
                acc[j].z += a * w.z; acc[j].w += a * w.w;
            }
        }
        // store h2 and compute head dots for the 4 heads in this half
        float* accf = (float*)acc;
#pragma unroll
        for (int j = 0; j < 8; j++)
            *(float4*)&g_h2[i * 64 + half * 32 + j * 4] = acc[j];
        float* asf = &as2v[half].x;
        float* adf = &ad2v[half].x;
#pragma unroll
        for (int h = 0; h < 4; h++) {
            int hd = half * 4 + h;
            float cs = 0.f, cd = 0.f;
#pragma unroll
            for (int c = 0; c < 8; c++) {
                float hv = accf[h * 8 + c];
                cs += hv * sAs[hd * 8 + c];
                cd += hv * sAd[hd * 8 + c];
            }
            asf[h] = cs;
            adf[h] = cd;
        }
    }
    *(float4*)&g_as2[i * 8]     = as2v[0];
    *(float4*)&g_as2[i * 8 + 4] = as2v[1];
    *(float4*)&g_ad2[i * 8]     = ad2v[0];
    *(float4*)&g_ad2[i * 8 + 4] = ad2v[1];

    float4 z = make_float4(0.f, 0.f, 0.f, 0.f);
    *(float4*)&g_s2[i * 8]     = z;
    *(float4*)&g_s2[i * 8 + 4] = z;
#pragma unroll
    for (int j = 0; j < 16; j++)
        *(float4*)&g_acc2[i * 64 + j * 4] = z;
}

// ---------------- layer 2: fused edge pass (2 threads/edge, 4 heads each) -----
__global__ void k_l2_edge(const int* __restrict__ src, const int* __restrict__ dst,
                          int E, int Etot) {
    int tid = blockIdx.x * blockDim.x + threadIdx.x;
    int e = tid >> 1;
    if (e >= Etot) return;
    int half = tid & 1;
    int s, d;
    if (e < E) { s = src[e]; d = dst[e]; } else { s = d = e - E; }
    float4 as = *(const float4*)&g_as2[s * 8 + half * 4];
    float4 ad = *(const float4*)&g_ad2[d * 8 + half * 4];
    float4 p;
    p.x = __expf(lrelu(as.x + ad.x));
    p.y = __expf(lrelu(as.y + ad.y));
    p.z = __expf(lrelu(as.z + ad.z));
    p.w = __expf(lrelu(as.w + ad.w));
    red_add_v4(&g_s2[d * 8 + half * 4], p);
    const float* pp = &p.x;
#pragma unroll
    for (int j = 0; j < 4; j++) {
        float pj = pp[j];
        int ch = (half * 4 + j) * 8;
        float4 h0 = *(const float4*)&g_h2[s * 64 + ch];
        float4 h1 = *(const float4*)&g_h2[s * 64 + ch + 4];
        red_add_v4(&g_acc2[d * 64 + ch],
                   make_float4(pj * h0.x, pj * h0.y, pj * h0.z, pj * h0.w));
        red_add_v4(&g_acc2[d * 64 + ch + 4],
                   make_float4(pj * h1.x, pj * h1.y, pj * h1.z, pj * h1.w));
    }
}

// ---------------- layer 2 finalize + FC (warp per node) ----------------------
__global__ void k_fin_fc(const float* __restrict__ bias2, const float* __restrict__ fcw,
                         const float* __restrict__ fcb, float* __restrict__ out, int N) {
    int t = blockIdx.x * blockDim.x + threadIdx.x;
    int i = t >> 5;
    if (i >= N) return;
    int lane = t & 31;
    int c = lane * 2;            // two adjacent channels, same head
    int hd = c >> 3;
    float inv = 1.f / (g_s2[i * 8 + hd] + EPS);
    float2 v = *(const float2*)&g_acc2[i * 64 + c];
    float e0 = elu(v.x * inv + __ldg(&bias2[c]));
    float e1 = elu(v.y * inv + __ldg(&bias2[c + 1]));
    float part = e0 * __ldg(&fcw[c]) + e1 * __ldg(&fcw[c + 1]);
#pragma unroll
    for (int o = 16; o > 0; o >>= 1)
        part += __shfl_xor_sync(0xffffffffu, part, o);
    if (lane == 0) out[i] = part + __ldg(&fcb[0]);
}

// ---------------- launch ------------------------------------------------------
extern "C" void kernel_launch(void* const* d_in, const int* in_sizes, int n_in,
                              void* d_out, int out_size) {
    const float* x    = (const float*)d_in[0];
    const int*   ei   = (const int*)  d_in[1];
    const float* W1   = (const float*)d_in[2];
    const float* as1  = (const float*)d_in[3];
    const float* ad1  = (const float*)d_in[4];
    const float* b1   = (const float*)d_in[5];
    const float* W2   = (const float*)d_in[6];
    const float* as2  = (const float*)d_in[7];
    const float* ad2  = (const float*)d_in[8];
    const float* b2   = (const float*)d_in[9];
    const float* fcw  = (const float*)d_in[10];
    const float* fcb  = (const float*)d_in[11];
    float* out = (float*)d_out;

    int N = in_sizes[0];          // x is [N, 1]
    int E = in_sizes[1] / 2;      // edge_index is [2, E]
    int Etot = E + N;             // + self loops
    const int* src = ei;
    const int* dst = ei + E;

    const int T = 256;
    k_l1_node<<<(N + T - 1) / T, T>>>(x, W1, as1, ad1, N);
    k_l1_edge<<<(Etot + T - 1) / T, T>>>(x, src, dst, E, Etot);
    k_mid    <<<(N + 127) / 128, 128>>>(W1, b1, W2, as2, ad2, N);
    k_l2_edge<<<((long)Etot * 2 + T - 1) / T, T>>>(src, dst, E, Etot);
    k_fin_fc <<<((long)N * 32 + T - 1) / T, T>>>(b2, fcw, fcb, out, N);
}

// round 8
// speedup vs baseline: 2.1119x; 2.1119x over previous
#include <cuda_runtime.h>
#include <cuda_bf16.h>

// Problem-fixed capacities (N=100000, E=1600000 per setup_inputs)
#define NMAX   100000
#define EMAX   1600000
#define ETOTMX (NMAX + EMAX)
#define EPS    1e-16f
#define SCAN_BLK 256
#define NSCANBLK ((NMAX + SCAN_BLK - 1) / SCAN_BLK)   // 391

// ---------------- scratch (static device globals; no allocation) -------------
__device__ __align__(16) float g_as1 [NMAX * 4];
__device__ __align__(16) float g_ad1 [NMAX * 4];
__device__ __align__(16) float g_base[NMAX * 4];   // t1/(s1+eps) per head
__device__ __align__(16) float g_h2  [NMAX * 64];
__device__ __align__(16) float g_as2 [NMAX * 8];
__device__ __align__(16) float g_ad2 [NMAX * 8];
__device__ int g_deg [NMAX];
__device__ int g_off [NMAX];
__device__ int g_cur [NMAX];
__device__ int g_csr [ETOTMX];     // src ids grouped by dst
__device__ int g_bsum[NSCANBLK];

__device__ __forceinline__ float lrelu(float t) { return t > 0.f ? t : 0.2f * t; }
__device__ __forceinline__ float elu(float t)   { return t > 0.f ? t : expm1f(t); }

// ---------------- layer 1 node-side coeffs + deg=1 (self loop) ---------------
__global__ void k_l1_node(const float* __restrict__ x, const float* __restrict__ W1,
                          const float* __restrict__ atts, const float* __restrict__ attd,
                          int N) {
    int i = blockIdx.x * blockDim.x + threadIdx.x;
    if (i >= N) return;
    float xv = x[i];
    float4 vs, vd;
    float* ps = &vs.x;
    float* pd = &vd.x;
#pragma unroll
    for (int hd = 0; hd < 4; hd++) {
        float cs = 0.f, cd = 0.f;
#pragma unroll
        for (int c = 0; c < 8; c++) {
            float w = __ldg(&W1[hd * 8 + c]);
            cs += w * __ldg(&atts[hd * 8 + c]);
            cd += w * __ldg(&attd[hd * 8 + c]);
        }
        ps[hd] = xv * cs;
        pd[hd] = xv * cd;
    }
    *(float4*)&g_as1[i * 4] = vs;
    *(float4*)&g_ad1[i * 4] = vd;
    g_deg[i] = 1;                      // self loop
}

// ---------------- CSR build: histogram ----------------------------------------
__global__ void k_hist(const int* __restrict__ dst, int E) {
    int e = blockIdx.x * blockDim.x + threadIdx.x;
    if (e < E) atomicAdd(&g_deg[dst[e]], 1);
}

// ---------------- CSR build: 2-level exclusive scan ---------------------------
__global__ void k_scanA(int N) {
    __shared__ int sm[SCAN_BLK];
    int i = blockIdx.x * SCAN_BLK + threadIdx.x;
    int v = (i < N) ? g_deg[i] : 0;
    sm[threadIdx.x] = v;
    __syncthreads();
#pragma unroll
    for (int o = 1; o < SCAN_BLK; o <<= 1) {
        int t = (threadIdx.x >= o) ? sm[threadIdx.x - o] : 0;
        __syncthreads();
        sm[threadIdx.x] += t;
        __syncthreads();
    }
    if (i < N) g_off[i] = sm[threadIdx.x] - v;               // exclusive in-block
    if (threadIdx.x == SCAN_BLK - 1) g_bsum[blockIdx.x] = sm[threadIdx.x];
}

__global__ void k_scanB() {
    __shared__ int sm[512];
    int v = (threadIdx.x < NSCANBLK) ? g_bsum[threadIdx.x] : 0;
    sm[threadIdx.x] = v;
    __syncthreads();
#pragma unroll
    for (int o = 1; o < 512; o <<= 1) {
        int t = (threadIdx.x >= o) ? sm[threadIdx.x - o] : 0;
        __syncthreads();
        sm[threadIdx.x] += t;
        __syncthreads();
    }
    if (threadIdx.x < NSCANBLK) g_bsum[threadIdx.x] = sm[threadIdx.x] - v;  // exclusive
}

__global__ void k_scanC(int N) {
    int i = blockIdx.x * blockDim.x + threadIdx.x;
    if (i >= N) return;
    int o = g_off[i] + g_bsum[i / SCAN_BLK];
    g_off[i] = o;
    g_cur[i] = o;
}

// ---------------- CSR build: fill ---------------------------------------------
__global__ void k_fill(const int* __restrict__ src, const int* __restrict__ dst,
                       int E, int Etot) {
    int e = blockIdx.x * blockDim.x + threadIdx.x;
    if (e >= Etot) return;
    int s, d;
    if (e < E) { s = src[e]; d = dst[e]; } else { s = d = e - E; }
    int pos = atomicAdd(&g_cur[d], 1);
    g_csr[pos] = s;
}

// ---------------- layer 1: gather-only aggregation (warp per node) ------------
// lanes: slot = lane>>2 (8 edge slots), hd = lane&3
__global__ void k_l1_gather(const float* __restrict__ x, int N) {
    int gw = (blockIdx.x * blockDim.x + threadIdx.x) >> 5;
    if (gw >= N) return;
    int lane = threadIdx.x & 31;
    int slot = lane >> 2, hd = lane & 3;
    int start = g_off[gw], deg = g_deg[gw];
    float ad = g_ad1[gw * 4 + hd];
    float psum = 0.f, tsum = 0.f;
    for (int k = slot; k < deg; k += 8) {
        int s = __ldg(&g_csr[start + k]);
        float as = __ldg(&g_as1[s * 4 + hd]);
        float p = __expf(lrelu(as + ad));
        psum += p;
        tsum += p * __ldg(&x[s]);
    }
#pragma unroll
    for (int o = 4; o < 32; o <<= 1) {
        psum += __shfl_xor_sync(0xffffffffu, psum, o);
        tsum += __shfl_xor_sync(0xffffffffu, tsum, o);
    }
    if (lane < 4) g_base[gw * 4 + hd] = tsum / (psum + EPS);
}

// ---------------- fused mid phase: one thread per node ------------------------
// act1 = elu(base * W1 + b1); h2 = act1 @ W2; as2/ad2 = head dots.
__global__ __launch_bounds__(128) void k_mid(const float* __restrict__ W1,
                                             const float* __restrict__ b1,
                                             const float* __restrict__ W2,
                                             const float* __restrict__ atts,
                                             const float* __restrict__ attd,
                                             int N) {
    __shared__ float sW1[32], sB1[32], sAs[64], sAd[64];
    __shared__ __align__(16) float sW2[32 * 64];
    for (int j = threadIdx.x; j < 32; j += blockDim.x) { sW1[j] = W1[j]; sB1[j] = b1[j]; }
    for (int j = threadIdx.x; j < 64; j += blockDim.x) { sAs[j] = atts[j]; sAd[j] = attd[j]; }
    for (int j = threadIdx.x; j < 32 * 64 / 4; j += blockDim.x)
        ((float4*)sW2)[j] = ((const float4*)W2)[j];
    __syncthreads();

    int i = blockIdx.x * blockDim.x + threadIdx.x;
    if (i >= N) return;

    float4 b4 = *(const float4*)&g_base[i * 4];
    const float* bp = &b4.x;
    float act[32];
#pragma unroll
    for (int hd = 0; hd < 4; hd++) {
        float base = bp[hd];
#pragma unroll
        for (int c = 0; c < 8; c++)
            act[hd * 8 + c] = elu(base * sW1[hd * 8 + c] + sB1[hd * 8 + c]);
    }

    float4 as2v[2], ad2v[2];
#pragma unroll
    for (int half = 0; half < 2; half++) {
        float4 acc[8];
#pragma unroll
        for (int j = 0; j < 8; j++) acc[j] = make_float4(0.f, 0.f, 0.f, 0.f);
#pragma unroll
        for (int k = 0; k < 32; k++) {
            float a = act[k];
            const float4* wrow = (const float4*)&sW2[k * 64 + half * 32];
#pragma unroll
            for (int j = 0; j < 8; j++) {
                float4 w = wrow[j];
                acc[j].x += a * w.x; acc[j].y += a * w.y;
                acc[j].z += a * w.z; acc[j].w += a * w.w;
            }
        }
        float* accf = (float*)acc;
#pragma unroll
        for (int j = 0; j < 8; j++)
            *(float4*)&g_h2[i * 64 + half * 32 + j * 4] = acc[j];
        float* asf = &as2v[half].x;
        float* adf = &ad2v[half].x;
#pragma unroll
        for (int h = 0; h < 4; h++) {
            int hd = half * 4 + h;
            float cs = 0.f, cd = 0.f;
#pragma unroll
            for (int c = 0; c < 8; c++) {
                float hv = accf[h * 8 + c];
                cs += hv * sAs[hd * 8 + c];
                cd += hv * sAd[hd * 8 + c];
            }
            asf[h] = cs;
            adf[h] = cd;
        }
    }
    *(float4*)&g_as2[i * 8]     = as2v[0];
    *(float4*)&g_as2[i * 8 + 4] = as2v[1];
    *(float4*)&g_ad2[i * 8]     = ad2v[0];
    *(float4*)&g_ad2[i * 8 + 4] = ad2v[1];
}

// ---------------- layer 2 gather + finalize + FC (warp per node) --------------
// lanes: slot = lane>>4 (2 edge slots), q = lane&15 -> channels q*4..q*4+3, head q>>1
__global__ void k_l2fc(const float* __restrict__ b2, const float* __restrict__ fcw,
                       const float* __restrict__ fcb, float* __restrict__ out, int N) {
    int gw = (blockIdx.x * blockDim.x + threadIdx.x) >> 5;
    if (gw >= N) return;
    int lane = threadIdx.x & 31;
    int slot = lane >> 4;
    int q = lane & 15;
    int ch = q * 4, hd = q >> 1;
    int start = g_off[gw], deg = g_deg[gw];
    float ad = g_ad2[gw * 8 + hd];
    float4 acc = make_float4(0.f, 0.f, 0.f, 0.f);
    float psum = 0.f;
    for (int k = slot; k < deg; k += 2) {
        int s = __ldg(&g_csr[start + k]);
        float as = __ldg(&g_as2[s * 8 + hd]);
        float p = __expf(lrelu(as + ad));
        float4 h = __ldg((const float4*)&g_h2[s * 64 + ch]);
        acc.x += p * h.x; acc.y += p * h.y;
        acc.z += p * h.z; acc.w += p * h.w;
        psum += p;
    }
    // combine the two edge slots (lanes differing in bit 4)
    acc.x += __shfl_xor_sync(0xffffffffu, acc.x, 16);
    acc.y += __shfl_xor_sync(0xffffffffu, acc.y, 16);
    acc.z += __shfl_xor_sync(0xffffffffu, acc.z, 16);
    acc.w += __shfl_xor_sync(0xffffffffu, acc.w, 16);
    psum  += __shfl_xor_sync(0xffffffffu, psum, 16);
    float inv = 1.f / (psum + EPS);
    float e0 = elu(acc.x * inv + __ldg(&b2[ch]));
    float e1 = elu(acc.y * inv + __ldg(&b2[ch + 1]));
    float e2 = elu(acc.z * inv + __ldg(&b2[ch + 2]));
    float e3 = elu(acc.w * inv + __ldg(&b2[ch + 3]));
    float part = e0 * __ldg(&fcw[ch])     + e1 * __ldg(&fcw[ch + 1])
               + e2 * __ldg(&fcw[ch + 2]) + e3 * __ldg(&fcw[ch + 3]);
    // reduce over the 16 channel-lanes (both halves hold identical data)
#pragma unroll
    for (int o = 8; o > 0; o >>= 1)
        part += __shfl_xor_sync(0xffffffffu, part, o);
    if (lane == 0) out[gw] = part + __ldg(&fcb[0]);
}

// ---------------- launch ------------------------------------------------------
extern "C" void kernel_launch(void* const* d_in, const int* in_sizes, int n_in,
                              void* d_out, int out_size) {
    const float* x    = (const float*)d_in[0];
    const int*   ei   = (const int*)  d_in[1];
    const float* W1   = (const float*)d_in[2];
    const float* as1  = (const float*)d_in[3];
    const float* ad1  = (const float*)d_in[4];
    const float* b1   = (const float*)d_in[5];
    const float* W2   = (const float*)d_in[6];
    const float* as2  = (const float*)d_in[7];
    const float* ad2  = (const float*)d_in[8];
    const float* b2   = (const float*)d_in[9];
    const float* fcw  = (const float*)d_in[10];
    const float* fcb  = (const float*)d_in[11];
    float* out = (float*)d_out;

    int N = in_sizes[0];          // x is [N, 1]
    int E = in_sizes[1] / 2;      // edge_index is [2, E]
    int Etot = E + N;             // + self loops
    const int* src = ei;
    const int* dst = ei + E;

    const int T = 256;
    k_l1_node  <<<(N + T - 1) / T, T>>>(x, W1, as1, ad1, N);
    k_hist     <<<(E + T - 1) / T, T>>>(dst, E);
    k_scanA    <<<NSCANBLK, SCAN_BLK>>>(N);
    k_scanB    <<<1, 512>>>();
    k_scanC    <<<(N + T - 1) / T, T>>>(N);
    k_fill     <<<(Etot + T - 1) / T, T>>>(src, dst, E, Etot);
    k_l1_gather<<<(int)(((long)N * 32 + T - 1) / T), T>>>(x, N);
    k_mid      <<<(N + 127) / 128, 128>>>(W1, b1, W2, as2, ad2, N);
    k_l2fc     <<<(int)(((long)N * 32 + T - 1) / T), T>>>(b2, fcw, fcb, out, N);
}